// round 10
// baseline (speedup 1.0000x reference)
#include <cuda_runtime.h>
#include <cuda_fp16.h>
#include <cstdint>
#include <cstddef>

#define S_LEN 2048
#define D_DIM 4096
#define H_NUM 32
#define HD_DIM 128
#define FF_DIM 11008

// ================= scratch (device globals; no allocations allowed) =========
__device__ __half g_hn  [(size_t)S_LEN * D_DIM];
__device__ __half g_q   [(size_t)S_LEN * D_DIM];
__device__ __half g_k   [(size_t)S_LEN * D_DIM];
__device__ __half g_v   [(size_t)S_LEN * D_DIM];
__device__ __half g_attn[(size_t)S_LEN * D_DIM];
__device__ float  g_h   [(size_t)S_LEN * D_DIM];
__device__ __half g_fn  [(size_t)S_LEN * D_DIM];
__device__ __half g_ff1 [(size_t)S_LEN * FF_DIM];
// fp16 weights (converted once per call)
__device__ __half g_wq16[(size_t)D_DIM * D_DIM];
__device__ __half g_wk16[(size_t)D_DIM * D_DIM];
__device__ __half g_wv16[(size_t)D_DIM * D_DIM];
__device__ __half g_wo16[(size_t)D_DIM * D_DIM];
__device__ __half g_w116[(size_t)D_DIM * FF_DIM];
__device__ __half g_w316[(size_t)D_DIM * FF_DIM];
__device__ __half g_w216[(size_t)FF_DIM * D_DIM];

// ================= helpers ===================================================
__device__ __forceinline__ uint32_t smem_u32(const void* p) {
    uint32_t a;
    asm("{ .reg .u64 t; cvta.to.shared.u64 t, %1; cvt.u32.u64 %0, t; }"
        : "=r"(a) : "l"(p));
    return a;
}
__device__ __forceinline__ void cp16(uint32_t dst, const void* src) {
    asm volatile("cp.async.cg.shared.global [%0], [%1], 16;"
                 :: "r"(dst), "l"(src) : "memory");
}
__device__ __forceinline__ void cp_commit() {
    asm volatile("cp.async.commit_group;" ::: "memory");
}
template<int N> __device__ __forceinline__ void cp_wait() {
    asm volatile("cp.async.wait_group %0;" :: "n"(N) : "memory");
}
__device__ __forceinline__ void mma_f16(
    float* c, const uint32_t* a, uint32_t b0, uint32_t b1)
{
    asm volatile(
        "mma.sync.aligned.m16n8k16.row.col.f32.f16.f16.f32 "
        "{%0,%1,%2,%3}, {%4,%5,%6,%7}, {%8,%9}, {%0,%1,%2,%3};"
        : "+f"(c[0]), "+f"(c[1]), "+f"(c[2]), "+f"(c[3])
        : "r"(a[0]), "r"(a[1]), "r"(a[2]), "r"(a[3]), "r"(b0), "r"(b1));
}
__device__ __forceinline__ void ldsm4(
    uint32_t& r0, uint32_t& r1, uint32_t& r2, uint32_t& r3, uint32_t addr)
{
    asm volatile("ldmatrix.sync.aligned.m8n8.x4.shared.b16 {%0,%1,%2,%3}, [%4];"
        : "=r"(r0), "=r"(r1), "=r"(r2), "=r"(r3) : "r"(addr));
}
__device__ __forceinline__ void ldsm4t(
    uint32_t& r0, uint32_t& r1, uint32_t& r2, uint32_t& r3, uint32_t addr)
{
    asm volatile("ldmatrix.sync.aligned.m8n8.x4.trans.shared.b16 {%0,%1,%2,%3}, [%4];"
        : "=r"(r0), "=r"(r1), "=r"(r2), "=r"(r3) : "r"(addr));
}
__device__ __forceinline__ uint32_t h2u(__half2 h) { return *(uint32_t*)&h; }
__device__ __forceinline__ float silu_f(float x) { return x / (1.0f + __expf(-x)); }

// ================= fp32 -> fp16 weight conversion ============================
__global__ void __launch_bounds__(256) cvt_f16(
    const float4* __restrict__ in, uint2* __restrict__ out, size_t n4)
{
    size_t i = (size_t)blockIdx.x * blockDim.x + threadIdx.x;
    const size_t stride = (size_t)gridDim.x * blockDim.x;
    for (; i < n4; i += stride) {
        float4 v = in[i];
        out[i] = make_uint2(h2u(__floats2half2_rn(v.x, v.y)),
                            h2u(__floats2half2_rn(v.z, v.w)));
    }
}

// ================= BIG fp16 GEMM: 128x256 tile, warp 64x64, ldmatrix ========
// A: fp16 [m][k]. B: fp16 [k][n]. BK=32, 3-stage cp.async, one sync/iter.
// Fragment loads batched per ks (8 LDSM then 32 HMMA) for latency hiding.
// smem/stage: A 128x40h (10240 B) + B 32x264h (16896 B) = 27136 B.
#define BIG_STAGE 27136
#define BIG_SMEM_BYTES (3 * BIG_STAGE)

template<int OUT_F16>
__global__ void __launch_bounds__(256) mma_big(
    const __half* __restrict__ A, int lda,
    const __half* __restrict__ B0, const __half* __restrict__ B1,
    const __half* __restrict__ B2, int ldb,
    void* __restrict__ C0, void* __restrict__ C1, void* __restrict__ C2,
    int ldc, int K,
    const float* __restrict__ res, int ldres,
    const __half* __restrict__ gate, int ldgate,
    const float* __restrict__ cosb, const float* __restrict__ sinb,
    int rope_mask)
{
    int sel = 0, bxl = blockIdx.x;
    if (B1) { sel = bxl >> 4; bxl &= 15; }
    const __half* __restrict__ B = (sel == 0) ? B0 : (sel == 1) ? B1 : B2;
    void* __restrict__ Cv = (sel == 0) ? C0 : (sel == 1) ? C1 : C2;
    const int dorope = (rope_mask >> sel) & 1;

    const int NIT = K >> 5;
    extern __shared__ char smch[];
    const uint32_t sbase = smem_u32(smch);

    const int tid = threadIdx.x;
    const int wid = tid >> 5, lane = tid & 31;
    const int gi = lane >> 2, ti = lane & 3;
    const int rowl = lane & 15, off8 = (lane >> 4) * 8;
    const int wm0 = (wid & 1) * 64;
    const int wn0 = (wid >> 1) * 64;
    const int m0 = blockIdx.y * 128, n0 = bxl * 256;

    auto load_tiles = [&](int k0, int s) {
        const uint32_t sA = sbase + s * BIG_STAGE;
        const uint32_t sB = sA + 10240;
#pragma unroll
        for (int t = 0; t < 2; t++) {                 // A: 128 rows x 32 halves
            int sid = tid + t * 256;
            int row = sid >> 2, seg = (sid & 3) * 8;
            cp16(sA + (row * 40 + seg) * 2,
                 A + (size_t)(m0 + row) * lda + k0 + seg);
        }
#pragma unroll
        for (int t = 0; t < 4; t++) {                 // B: 32 rows x 256 halves
            int sid = tid + t * 256;
            int row = sid >> 5, seg = (sid & 31) * 8;
            cp16(sB + (row * 264 + seg) * 2,
                 B + (size_t)(k0 + row) * ldb + n0 + seg);
        }
        cp_commit();
    };

    float acc[4][8][4];
#pragma unroll
    for (int i = 0; i < 4; i++)
#pragma unroll
        for (int j = 0; j < 8; j++)
#pragma unroll
            for (int r = 0; r < 4; r++) acc[i][j][r] = 0.f;

    load_tiles(0, 0);
    load_tiles(32, 1);

    for (int it = 0; it < NIT; it++) {
        const int st = it % 3;
        if (it + 1 < NIT) cp_wait<1>(); else cp_wait<0>();
        __syncthreads();
        if (it + 2 < NIT) {
            int nx = it + 2;
            load_tiles(nx * 32, nx % 3);
        }

        const uint32_t sA = sbase + st * BIG_STAGE;
        const uint32_t sB = sA + 10240;
#pragma unroll
        for (int ks = 0; ks < 2; ks++) {
            // ---- batch all 8 LDSM first (one latency bubble per 32 MMAs) --
            uint32_t a[4][4], b[4][4];
#pragma unroll
            for (int mi = 0; mi < 4; mi++)
                ldsm4(a[mi][0], a[mi][1], a[mi][2], a[mi][3],
                      sA + ((wm0 + mi * 16 + rowl) * 40 + ks * 16 + off8) * 2);
#pragma unroll
            for (int p = 0; p < 4; p++)
                ldsm4t(b[p][0], b[p][1], b[p][2], b[p][3],
                       sB + ((ks * 16 + rowl) * 264 + wn0 + p * 16 + off8) * 2);
            // ---- then 32 MMAs back-to-back --------------------------------
#pragma unroll
            for (int p = 0; p < 4; p++)
#pragma unroll
                for (int mi = 0; mi < 4; mi++) {
                    mma_f16(acc[mi][2 * p],     a[mi], b[p][0], b[p][1]);
                    mma_f16(acc[mi][2 * p + 1], a[mi], b[p][2], b[p][3]);
                }
        }
    }

    // ---- epilogue ----------------------------------------------------------
#pragma unroll
    for (int mi = 0; mi < 4; mi++) {
#pragma unroll
        for (int ni = 0; ni < 8; ni++) {
            const int row = m0 + wm0 + mi * 16 + gi;
            const int col = n0 + wn0 + ni * 8 + ti * 2;
            float v0 = acc[mi][ni][0];
            float v1 = acc[mi][ni][1];
            float v2 = acc[mi][ni][2];
            float v3 = acc[mi][ni][3];
            if (OUT_F16) {
                __half* C = (__half*)Cv;
                if (dorope) {
                    const int j = (col & 127) >> 1;
                    const float c0 = cosb[row * 64 + j], s0 = sinb[row * 64 + j];
                    const float c1 = cosb[(row + 8) * 64 + j], s1 = sinb[(row + 8) * 64 + j];
                    float t0 = v0 * c0 - v1 * s0, t1 = v0 * s0 + v1 * c0;
                    float t2 = v2 * c1 - v3 * s1, t3 = v2 * s1 + v3 * c1;
                    v0 = t0; v1 = t1; v2 = t2; v3 = t3;
                }
                if (gate) {
                    __half2 g0 = *(const __half2*)&gate[(size_t)row * ldgate + col];
                    __half2 g1 = *(const __half2*)&gate[(size_t)(row + 8) * ldgate + col];
                    v0 *= silu_f(__low2float(g0));  v1 *= silu_f(__high2float(g0));
                    v2 *= silu_f(__low2float(g1));  v3 *= silu_f(__high2float(g1));
                }
                *(__half2*)&C[(size_t)row * ldc + col]       = __floats2half2_rn(v0, v1);
                *(__half2*)&C[(size_t)(row + 8) * ldc + col] = __floats2half2_rn(v2, v3);
            } else {
                float* C = (float*)Cv;
                if (res) {
                    float2 r0 = *(const float2*)&res[(size_t)row * ldres + col];
                    float2 r1 = *(const float2*)&res[(size_t)(row + 8) * ldres + col];
                    v0 += r0.x; v1 += r0.y; v2 += r1.x; v3 += r1.y;
                }
                *(float2*)&C[(size_t)row * ldc + col]       = make_float2(v0, v1);
                *(float2*)&C[(size_t)(row + 8) * ldc + col] = make_float2(v2, v3);
            }
        }
    }
}

// ================= flash attention (fp16, ldmatrix, 3-stage KV) =============
#define FAH_STAGE 34816
#define FAH_P_OFF (3 * FAH_STAGE)
#define FAH_SMEM_BYTES (FAH_P_OFF + 128 * 72 * 2)

__global__ void __launch_bounds__(256) flash_attn(
    const __half* __restrict__ Q, const __half* __restrict__ K,
    const __half* __restrict__ V, __half* __restrict__ O)
{
    const int by = blockIdx.x;
    const int h  = blockIdx.y;
    const int m0 = by * 128;
    const int NKT = 2 * (by + 1);

    extern __shared__ char smch[];
    const uint32_t sbase = smem_u32(smch);

    const int tid = threadIdx.x;
    const int wid = tid >> 5, lane = tid & 31;
    const int gi = lane >> 2, ti = lane & 3;
    const int rowl = lane & 15, off8 = (lane >> 4) * 8;
    const int keyrow = (lane & 7) | (((lane >> 4) & 1) << 3);
    const int doff   = ((lane >> 3) & 1) * 8;
    const int wr = wid * 16;

    // ---- stage Q tile (128x128 halves, stride 136) ------------------------
#pragma unroll
    for (int t = 0; t < 8; t++) {
        int sid = tid + t * 256;
        int row = sid >> 4, seg = (sid & 15) * 8;
        cp16(sbase + (row * 136 + seg) * 2,
             Q + (size_t)(m0 + row) * D_DIM + h * HD_DIM + seg);
    }
    cp_commit();
    cp_wait<0>();
    __syncthreads();

    uint32_t qf[8][4];
#pragma unroll
    for (int ks = 0; ks < 8; ks++)
        ldsm4(qf[ks][0], qf[ks][1], qf[ks][2], qf[ks][3],
              sbase + ((wr + rowl) * 136 + ks * 16 + off8) * 2);
    __syncthreads();

    auto load_kv = [&](int kt, int s) {
        const uint32_t sK = sbase + s * FAH_STAGE;
        const uint32_t sV = sK + 64 * 136 * 2;
        const int kb = kt * 64;
#pragma unroll
        for (int t = 0; t < 4; t++) {
            int sid = tid + t * 256;
            int row = sid >> 4, seg = (sid & 15) * 8;
            cp16(sK + (row * 136 + seg) * 2,
                 K + (size_t)(kb + row) * D_DIM + h * HD_DIM + seg);
            cp16(sV + (row * 136 + seg) * 2,
                 V + (size_t)(kb + row) * D_DIM + h * HD_DIM + seg);
        }
        cp_commit();
    };

    load_kv(0, 0);
    if (NKT > 1) load_kv(1, 1);

    float o[16][4];
#pragma unroll
    for (int i = 0; i < 16; i++)
#pragma unroll
        for (int r = 0; r < 4; r++) o[i][r] = 0.f;
    float ls0 = 0.f, ls1 = 0.f;
    const float SC = 0.08838834764831845f;     // 1/sqrt(128)

    const int r0 = m0 + wr + gi, r1 = r0 + 8;

    for (int kt = 0; kt < NKT; kt++) {
        const int st = kt % 3;
        if (kt + 1 < NKT) cp_wait<1>(); else cp_wait<0>();
        __syncthreads();
        if (kt + 2 < NKT) {
            int nx = kt + 2;
            load_kv(nx, nx % 3);
        }

        const uint32_t sKa = sbase + st * FAH_STAGE;
        const uint32_t sVa = sKa + 64 * 136 * 2;
        const uint32_t sPa = sbase + FAH_P_OFF;
        __half* sP = (__half*)(smch + FAH_P_OFF);

        // ---- S = Q @ K^T (batched K-fragment loads per ks) -----------------
        float c[8][4];
#pragma unroll
        for (int i = 0; i < 8; i++)
#pragma unroll
            for (int r = 0; r < 4; r++) c[i][r] = 0.f;
#pragma unroll
        for (int ks = 0; ks < 8; ks++) {
            uint32_t b[4][4];
#pragma unroll
            for (int p = 0; p < 4; p++)
                ldsm4(b[p][0], b[p][1], b[p][2], b[p][3],
                      sKa + ((p * 16 + keyrow) * 136 + ks * 16 + doff) * 2);
#pragma unroll
            for (int p = 0; p < 4; p++) {
                mma_f16(c[2 * p],     qf[ks], b[p][0], b[p][1]);
                mma_f16(c[2 * p + 1], qf[ks], b[p][2], b[p][3]);
            }
        }

        // ---- mask, p = exp(s*SC)/16, sum l, store P fp16 -------------------
        const int cb = kt * 64;
        const bool diag = (kt >= 2 * by);
#pragma unroll
        for (int ni = 0; ni < 8; ni++) {
            const int col = cb + ni * 8 + ti * 2;
            float s0 = c[ni][0], s1 = c[ni][1], s2 = c[ni][2], s3 = c[ni][3];
            if (diag) {
                if (col > r0)     s0 = -1e30f;
                if (col + 1 > r0) s1 = -1e30f;
                if (col > r1)     s2 = -1e30f;
                if (col + 1 > r1) s3 = -1e30f;
            }
            const float p0 = __expf(s0 * SC) * 0.0625f;
            const float p1 = __expf(s1 * SC) * 0.0625f;
            const float p2 = __expf(s2 * SC) * 0.0625f;
            const float p3 = __expf(s3 * SC) * 0.0625f;
            ls0 += p0 + p1;
            ls1 += p2 + p3;
            *(__half2*)&sP[(wr + gi) * 72 + ni * 8 + ti * 2]     = __floats2half2_rn(p0, p1);
            *(__half2*)&sP[(wr + gi + 8) * 72 + ni * 8 + ti * 2] = __floats2half2_rn(p2, p3);
        }
        __syncwarp();   // P region is warp-private; order STS before ldmatrix

        // ---- O += P @ V (batched V-fragment loads, 4 per halfgroup) --------
#pragma unroll
        for (int ks = 0; ks < 4; ks++) {
            uint32_t a[4];
            ldsm4(a[0], a[1], a[2], a[3],
                  sPa + ((wr + rowl) * 72 + ks * 16 + off8) * 2);
#pragma unroll
            for (int g = 0; g < 2; g++) {
                uint32_t vb[4][4];
#pragma unroll
                for (int p = 0; p < 4; p++)
                    ldsm4t(vb[p][0], vb[p][1], vb[p][2], vb[p][3],
                           sVa + ((ks * 16 + rowl) * 136 + (g * 4 + p) * 16 + off8) * 2);
#pragma unroll
                for (int p = 0; p < 4; p++) {
                    mma_f16(o[2 * (g * 4 + p)],     a, vb[p][0], vb[p][1]);
                    mma_f16(o[2 * (g * 4 + p) + 1], a, vb[p][2], vb[p][3]);
                }
            }
        }
    }

    // ---- normalize + store fp16 (1/16 scale cancels: O/ls) -----------------
    ls0 += __shfl_xor_sync(0xffffffffu, ls0, 1);
    ls0 += __shfl_xor_sync(0xffffffffu, ls0, 2);
    ls1 += __shfl_xor_sync(0xffffffffu, ls1, 1);
    ls1 += __shfl_xor_sync(0xffffffffu, ls1, 2);
    const float i0 = 1.0f / ls0, i1 = 1.0f / ls1;
#pragma unroll
    for (int ni = 0; ni < 16; ni++) {
        const int col = h * HD_DIM + ni * 8 + ti * 2;
        *(__half2*)&O[(size_t)r0 * D_DIM + col] =
            __floats2half2_rn(o[ni][0] * i0, o[ni][1] * i0);
        *(__half2*)&O[(size_t)r1 * D_DIM + col] =
            __floats2half2_rn(o[ni][2] * i1, o[ni][3] * i1);
    }
}

// ================= rmsnorm: fp32 in -> fp16 out ==============================
__global__ void __launch_bounds__(256) rmsnorm_f16(
    const float* __restrict__ X, const float* __restrict__ W,
    __half* __restrict__ Y)
{
    const int row = blockIdx.x;
    const float* x = X + (size_t)row * D_DIM;
    float ss = 0.f;
    for (int j = threadIdx.x; j < D_DIM; j += 256) { float v = x[j]; ss += v * v; }
    __shared__ float red[256];
    red[threadIdx.x] = ss;
    __syncthreads();
    for (int off = 128; off > 0; off >>= 1) {
        if (threadIdx.x < off) red[threadIdx.x] += red[threadIdx.x + off];
        __syncthreads();
    }
    const float scale = rsqrtf(red[0] * (1.0f / D_DIM) + 1e-6f);
    __half* y = Y + (size_t)row * D_DIM;
    for (int j = threadIdx.x * 2; j < D_DIM; j += 512) {
        float2 v = *(const float2*)&x[j];
        *(__half2*)&y[j] = __floats2half2_rn(v.x * scale * W[j],
                                             v.y * scale * W[j + 1]);
    }
}

// ================= launch =====================================================
extern "C" void kernel_launch(void* const* d_in, const int* in_sizes, int n_in,
                              void* d_out, int out_size)
{
    const float* x    = (const float*)d_in[0];
    const float* wq   = (const float*)d_in[1];
    const float* wk   = (const float*)d_in[2];
    const float* wv   = (const float*)d_in[3];
    const float* wo   = (const float*)d_in[4];
    const float* w1   = (const float*)d_in[5];
    const float* w2   = (const float*)d_in[6];
    const float* w3   = (const float*)d_in[7];
    const float* anw  = (const float*)d_in[8];
    const float* fnw  = (const float*)d_in[9];
    const float* cosb = (const float*)d_in[10];
    const float* sinb = (const float*)d_in[11];
    float* out = (float*)d_out;

    __half *hn, *q, *k, *v, *attn, *fn, *ff1;
    __half *wq16, *wk16, *wv16, *wo16, *w116, *w316, *w216;
    float *h;
    cudaGetSymbolAddress((void**)&hn, g_hn);
    cudaGetSymbolAddress((void**)&q, g_q);
    cudaGetSymbolAddress((void**)&k, g_k);
    cudaGetSymbolAddress((void**)&v, g_v);
    cudaGetSymbolAddress((void**)&attn, g_attn);
    cudaGetSymbolAddress((void**)&h, g_h);
    cudaGetSymbolAddress((void**)&fn, g_fn);
    cudaGetSymbolAddress((void**)&ff1, g_ff1);
    cudaGetSymbolAddress((void**)&wq16, g_wq16);
    cudaGetSymbolAddress((void**)&wk16, g_wk16);
    cudaGetSymbolAddress((void**)&wv16, g_wv16);
    cudaGetSymbolAddress((void**)&wo16, g_wo16);
    cudaGetSymbolAddress((void**)&w116, g_w116);
    cudaGetSymbolAddress((void**)&w316, g_w316);
    cudaGetSymbolAddress((void**)&w216, g_w216);

    cudaFuncSetAttribute(mma_big<0>,
                         cudaFuncAttributeMaxDynamicSharedMemorySize, BIG_SMEM_BYTES);
    cudaFuncSetAttribute(mma_big<1>,
                         cudaFuncAttributeMaxDynamicSharedMemorySize, BIG_SMEM_BYTES);
    cudaFuncSetAttribute(flash_attn,
                         cudaFuncAttributeMaxDynamicSharedMemorySize, FAH_SMEM_BYTES);

    // 0) convert weights to fp16 (once per call)
    const size_t nd4 = (size_t)D_DIM * D_DIM / 4, nf4 = (size_t)D_DIM * FF_DIM / 4;
    cvt_f16<<<4096, 256>>>((const float4*)wq, (uint2*)wq16, nd4);
    cvt_f16<<<4096, 256>>>((const float4*)wk, (uint2*)wk16, nd4);
    cvt_f16<<<4096, 256>>>((const float4*)wv, (uint2*)wv16, nd4);
    cvt_f16<<<4096, 256>>>((const float4*)wo, (uint2*)wo16, nd4);
    cvt_f16<<<8192, 256>>>((const float4*)w1, (uint2*)w116, nf4);
    cvt_f16<<<8192, 256>>>((const float4*)w3, (uint2*)w316, nf4);
    cvt_f16<<<8192, 256>>>((const float4*)w2, (uint2*)w216, nf4);

    // 1) attn rmsnorm -> fp16
    rmsnorm_f16<<<S_LEN, 256>>>(x, anw, hn);

    // 2) fused QKV projection (RoPE fused for q,k)
    mma_big<1><<<dim3(48, S_LEN / 128), 256, BIG_SMEM_BYTES>>>(
        hn, D_DIM, wq16, wk16, wv16, D_DIM, q, k, v, D_DIM, D_DIM,
        nullptr, 0, nullptr, 0, cosb, sinb, /*rope_mask=*/0b011);

    // 3) fused attention
    flash_attn<<<dim3(S_LEN / 128, H_NUM), 256, FAH_SMEM_BYTES>>>(q, k, v, attn);

    // 4) h = x + attn @ wo   (fp32 out)
    mma_big<0><<<dim3(16, S_LEN / 128), 256, BIG_SMEM_BYTES>>>(
        attn, D_DIM, wo16, nullptr, nullptr, D_DIM, h, nullptr, nullptr, D_DIM,
        D_DIM, x, D_DIM, nullptr, 0, nullptr, nullptr, 0);

    // 5) ffn rmsnorm -> fp16
    rmsnorm_f16<<<S_LEN, 256>>>(h, fnw, fn);

    // 6) FFN up: ff1 = fn@w1 ; then ff1 = silu(ff1) * (fn@w3)
    const dim3 gff(FF_DIM / 256, S_LEN / 128);
    mma_big<1><<<gff, 256, BIG_SMEM_BYTES>>>(
        fn, D_DIM, w116, nullptr, nullptr, FF_DIM, ff1, nullptr, nullptr, FF_DIM,
        D_DIM, nullptr, 0, nullptr, 0, nullptr, nullptr, 0);
    mma_big<1><<<gff, 256, BIG_SMEM_BYTES>>>(
        fn, D_DIM, w316, nullptr, nullptr, FF_DIM, ff1, nullptr, nullptr, FF_DIM,
        D_DIM, nullptr, 0, ff1, FF_DIM, nullptr, nullptr, 0);

    // 7) out = h + gated @ w2  (fp32 out)
    mma_big<0><<<dim3(16, S_LEN / 128), 256, BIG_SMEM_BYTES>>>(
        ff1, FF_DIM, w216, nullptr, nullptr, D_DIM, out, nullptr, nullptr, D_DIM,
        FF_DIM, h, D_DIM, nullptr, 0, nullptr, nullptr, 0);
}

// round 11
// speedup vs baseline: 1.0488x; 1.0488x over previous
#include <cuda_runtime.h>
#include <cuda_fp16.h>
#include <cstdint>
#include <cstddef>

#define S_LEN 2048
#define D_DIM 4096
#define H_NUM 32
#define HD_DIM 128
#define FF_DIM 11008

// ================= scratch (device globals; no allocations allowed) =========
__device__ __half g_hn  [(size_t)S_LEN * D_DIM];
__device__ __half g_q   [(size_t)S_LEN * D_DIM];
__device__ __half g_k   [(size_t)S_LEN * D_DIM];
__device__ __half g_v   [(size_t)S_LEN * D_DIM];
__device__ __half g_attn[(size_t)S_LEN * D_DIM];
__device__ float  g_h   [(size_t)S_LEN * D_DIM];
__device__ __half g_fn  [(size_t)S_LEN * D_DIM];
__device__ __half g_ff1 [(size_t)S_LEN * FF_DIM];
// fp16 weights (converted once per call)
__device__ __half g_wq16[(size_t)D_DIM * D_DIM];
__device__ __half g_wk16[(size_t)D_DIM * D_DIM];
__device__ __half g_wv16[(size_t)D_DIM * D_DIM];
__device__ __half g_wo16[(size_t)D_DIM * D_DIM];
__device__ __half g_w116[(size_t)D_DIM * FF_DIM];
__device__ __half g_w316[(size_t)D_DIM * FF_DIM];
__device__ __half g_w216[(size_t)FF_DIM * D_DIM];

// ================= helpers ===================================================
__device__ __forceinline__ uint32_t smem_u32(const void* p) {
    uint32_t a;
    asm("{ .reg .u64 t; cvta.to.shared.u64 t, %1; cvt.u32.u64 %0, t; }"
        : "=r"(a) : "l"(p));
    return a;
}
__device__ __forceinline__ void cp16(uint32_t dst, const void* src) {
    asm volatile("cp.async.cg.shared.global [%0], [%1], 16;"
                 :: "r"(dst), "l"(src) : "memory");
}
__device__ __forceinline__ void cp_commit() {
    asm volatile("cp.async.commit_group;" ::: "memory");
}
template<int N> __device__ __forceinline__ void cp_wait() {
    asm volatile("cp.async.wait_group %0;" :: "n"(N) : "memory");
}
__device__ __forceinline__ void mma_f16(
    float* c, const uint32_t* a, uint32_t b0, uint32_t b1)
{
    asm volatile(
        "mma.sync.aligned.m16n8k16.row.col.f32.f16.f16.f32 "
        "{%0,%1,%2,%3}, {%4,%5,%6,%7}, {%8,%9}, {%0,%1,%2,%3};"
        : "+f"(c[0]), "+f"(c[1]), "+f"(c[2]), "+f"(c[3])
        : "r"(a[0]), "r"(a[1]), "r"(a[2]), "r"(a[3]), "r"(b0), "r"(b1));
}
__device__ __forceinline__ void ldsm4(
    uint32_t& r0, uint32_t& r1, uint32_t& r2, uint32_t& r3, uint32_t addr)
{
    asm volatile("ldmatrix.sync.aligned.m8n8.x4.shared.b16 {%0,%1,%2,%3}, [%4];"
        : "=r"(r0), "=r"(r1), "=r"(r2), "=r"(r3) : "r"(addr));
}
__device__ __forceinline__ void ldsm4t(
    uint32_t& r0, uint32_t& r1, uint32_t& r2, uint32_t& r3, uint32_t addr)
{
    asm volatile("ldmatrix.sync.aligned.m8n8.x4.trans.shared.b16 {%0,%1,%2,%3}, [%4];"
        : "=r"(r0), "=r"(r1), "=r"(r2), "=r"(r3) : "r"(addr));
}
__device__ __forceinline__ uint32_t h2u(__half2 h) { return *(uint32_t*)&h; }
__device__ __forceinline__ float silu_f(float x) { return x / (1.0f + __expf(-x)); }

// ================= fp32 -> fp16 weight conversion ============================
__global__ void __launch_bounds__(256) cvt_f16(
    const float4* __restrict__ in, uint2* __restrict__ out, size_t n4)
{
    size_t i = (size_t)blockIdx.x * blockDim.x + threadIdx.x;
    const size_t stride = (size_t)gridDim.x * blockDim.x;
    for (; i < n4; i += stride) {
        float4 v = in[i];
        out[i] = make_uint2(h2u(__floats2half2_rn(v.x, v.y)),
                            h2u(__floats2half2_rn(v.z, v.w)));
    }
}

// ================= BIG fp16 GEMM: 128x256 tile, warp 64x64, ldmatrix ========
// A: fp16 [m][k]. B: fp16 [k][n]. BK=32, 3-stage cp.async, one sync/iter.
// smem/stage: A 128x40h (10240 B) + B 32x264h (16896 B) = 27136 B.
#define BIG_STAGE 27136
#define BIG_SMEM_BYTES (3 * BIG_STAGE)

template<int OUT_F16>
__global__ void __launch_bounds__(256) mma_big(
    const __half* __restrict__ A, int lda,
    const __half* __restrict__ B0, const __half* __restrict__ B1,
    const __half* __restrict__ B2, int ldb,
    void* __restrict__ C0, void* __restrict__ C1, void* __restrict__ C2,
    int ldc, int K,
    const float* __restrict__ res, int ldres,
    const __half* __restrict__ gate, int ldgate,
    const float* __restrict__ cosb, const float* __restrict__ sinb,
    int rope_mask)
{
    int sel = 0, bxl = blockIdx.x;
    if (B1) { sel = bxl >> 4; bxl &= 15; }
    const __half* __restrict__ B = (sel == 0) ? B0 : (sel == 1) ? B1 : B2;
    void* __restrict__ Cv = (sel == 0) ? C0 : (sel == 1) ? C1 : C2;
    const int dorope = (rope_mask >> sel) & 1;

    const int NIT = K >> 5;
    extern __shared__ char smch[];
    const uint32_t sbase = smem_u32(smch);

    const int tid = threadIdx.x;
    const int wid = tid >> 5, lane = tid & 31;
    const int gi = lane >> 2, ti = lane & 3;
    const int rowl = lane & 15, off8 = (lane >> 4) * 8;
    const int wm0 = (wid & 1) * 64;
    const int wn0 = (wid >> 1) * 64;
    const int m0 = blockIdx.y * 128, n0 = bxl * 256;

    auto load_tiles = [&](int k0, int s) {
        const uint32_t sA = sbase + s * BIG_STAGE;
        const uint32_t sB = sA + 10240;
#pragma unroll
        for (int t = 0; t < 2; t++) {                 // A: 128 rows x 32 halves
            int sid = tid + t * 256;
            int row = sid >> 2, seg = (sid & 3) * 8;
            cp16(sA + (row * 40 + seg) * 2,
                 A + (size_t)(m0 + row) * lda + k0 + seg);
        }
#pragma unroll
        for (int t = 0; t < 4; t++) {                 // B: 32 rows x 256 halves
            int sid = tid + t * 256;
            int row = sid >> 5, seg = (sid & 31) * 8;
            cp16(sB + (row * 264 + seg) * 2,
                 B + (size_t)(k0 + row) * ldb + n0 + seg);
        }
        cp_commit();
    };

    float acc[4][8][4];
#pragma unroll
    for (int i = 0; i < 4; i++)
#pragma unroll
        for (int j = 0; j < 8; j++)
#pragma unroll
            for (int r = 0; r < 4; r++) acc[i][j][r] = 0.f;

    load_tiles(0, 0);
    load_tiles(32, 1);

    for (int it = 0; it < NIT; it++) {
        const int st = it % 3;
        if (it + 1 < NIT) cp_wait<1>(); else cp_wait<0>();
        __syncthreads();
        if (it + 2 < NIT) {
            int nx = it + 2;
            load_tiles(nx * 32, nx % 3);
        }

        const uint32_t sA = sbase + st * BIG_STAGE;
        const uint32_t sB = sA + 10240;
#pragma unroll
        for (int ks = 0; ks < 2; ks++) {
            uint32_t a[4][4], b[4][4];
#pragma unroll
            for (int mi = 0; mi < 4; mi++)
                ldsm4(a[mi][0], a[mi][1], a[mi][2], a[mi][3],
                      sA + ((wm0 + mi * 16 + rowl) * 40 + ks * 16 + off8) * 2);
#pragma unroll
            for (int p = 0; p < 4; p++)
                ldsm4t(b[p][0], b[p][1], b[p][2], b[p][3],
                       sB + ((ks * 16 + rowl) * 264 + wn0 + p * 16 + off8) * 2);
#pragma unroll
            for (int p = 0; p < 4; p++)
#pragma unroll
                for (int mi = 0; mi < 4; mi++) {
                    mma_f16(acc[mi][2 * p],     a[mi], b[p][0], b[p][1]);
                    mma_f16(acc[mi][2 * p + 1], a[mi], b[p][2], b[p][3]);
                }
        }
    }

    // ---- epilogue ----------------------------------------------------------
#pragma unroll
    for (int mi = 0; mi < 4; mi++) {
#pragma unroll
        for (int ni = 0; ni < 8; ni++) {
            const int row = m0 + wm0 + mi * 16 + gi;
            const int col = n0 + wn0 + ni * 8 + ti * 2;
            float v0 = acc[mi][ni][0];
            float v1 = acc[mi][ni][1];
            float v2 = acc[mi][ni][2];
            float v3 = acc[mi][ni][3];
            if (OUT_F16) {
                __half* C = (__half*)Cv;
                if (dorope) {
                    const int j = (col & 127) >> 1;
                    const float c0 = cosb[row * 64 + j], s0 = sinb[row * 64 + j];
                    const float c1 = cosb[(row + 8) * 64 + j], s1 = sinb[(row + 8) * 64 + j];
                    float t0 = v0 * c0 - v1 * s0, t1 = v0 * s0 + v1 * c0;
                    float t2 = v2 * c1 - v3 * s1, t3 = v2 * s1 + v3 * c1;
                    v0 = t0; v1 = t1; v2 = t2; v3 = t3;
                }
                if (gate) {
                    __half2 g0 = *(const __half2*)&gate[(size_t)row * ldgate + col];
                    __half2 g1 = *(const __half2*)&gate[(size_t)(row + 8) * ldgate + col];
                    v0 *= silu_f(__low2float(g0));  v1 *= silu_f(__high2float(g0));
                    v2 *= silu_f(__low2float(g1));  v3 *= silu_f(__high2float(g1));
                }
                *(__half2*)&C[(size_t)row * ldc + col]       = __floats2half2_rn(v0, v1);
                *(__half2*)&C[(size_t)(row + 8) * ldc + col] = __floats2half2_rn(v2, v3);
            } else {
                float* C = (float*)Cv;
                if (res) {
                    float2 r0 = *(const float2*)&res[(size_t)row * ldres + col];
                    float2 r1 = *(const float2*)&res[(size_t)(row + 8) * ldres + col];
                    v0 += r0.x; v1 += r0.y; v2 += r1.x; v3 += r1.y;
                }
                *(float2*)&C[(size_t)row * ldc + col]       = make_float2(v0, v1);
                *(float2*)&C[(size_t)(row + 8) * ldc + col] = make_float2(v2, v3);
            }
        }
    }
}

// ================= flash attention (fp16, ldmatrix, heavy-first order) ======
#define FAH_STAGE 34816
#define FAH_P_OFF (3 * FAH_STAGE)
#define FAH_SMEM_BYTES (FAH_P_OFF + 128 * 72 * 2)

__global__ void __launch_bounds__(256) flash_attn(
    const __half* __restrict__ Q, const __half* __restrict__ K,
    const __half* __restrict__ V, __half* __restrict__ O)
{
    // 1D grid, heaviest q-tiles (largest causal span) scheduled first.
    const int bid = blockIdx.x;
    const int h  = bid & 31;
    const int by = 15 - (bid >> 5);
    const int m0 = by * 128;
    const int NKT = 2 * (by + 1);

    extern __shared__ char smch[];
    const uint32_t sbase = smem_u32(smch);

    const int tid = threadIdx.x;
    const int wid = tid >> 5, lane = tid & 31;
    const int gi = lane >> 2, ti = lane & 3;
    const int rowl = lane & 15, off8 = (lane >> 4) * 8;
    const int keyrow = (lane & 7) | (((lane >> 4) & 1) << 3);
    const int doff   = ((lane >> 3) & 1) * 8;
    const int wr = wid * 16;

    // ---- stage Q tile (128x128 halves, stride 136) ------------------------
#pragma unroll
    for (int t = 0; t < 8; t++) {
        int sid = tid + t * 256;
        int row = sid >> 4, seg = (sid & 15) * 8;
        cp16(sbase + (row * 136 + seg) * 2,
             Q + (size_t)(m0 + row) * D_DIM + h * HD_DIM + seg);
    }
    cp_commit();
    cp_wait<0>();
    __syncthreads();

    uint32_t qf[8][4];
#pragma unroll
    for (int ks = 0; ks < 8; ks++)
        ldsm4(qf[ks][0], qf[ks][1], qf[ks][2], qf[ks][3],
              sbase + ((wr + rowl) * 136 + ks * 16 + off8) * 2);
    __syncthreads();

    auto load_kv = [&](int kt, int s) {
        const uint32_t sK = sbase + s * FAH_STAGE;
        const uint32_t sV = sK + 64 * 136 * 2;
        const int kb = kt * 64;
#pragma unroll
        for (int t = 0; t < 4; t++) {
            int sid = tid + t * 256;
            int row = sid >> 4, seg = (sid & 15) * 8;
            cp16(sK + (row * 136 + seg) * 2,
                 K + (size_t)(kb + row) * D_DIM + h * HD_DIM + seg);
            cp16(sV + (row * 136 + seg) * 2,
                 V + (size_t)(kb + row) * D_DIM + h * HD_DIM + seg);
        }
        cp_commit();
    };

    load_kv(0, 0);
    if (NKT > 1) load_kv(1, 1);

    float o[16][4];
#pragma unroll
    for (int i = 0; i < 16; i++)
#pragma unroll
        for (int r = 0; r < 4; r++) o[i][r] = 0.f;
    float ls0 = 0.f, ls1 = 0.f;
    const float SC = 0.08838834764831845f;     // 1/sqrt(128)

    const int r0 = m0 + wr + gi, r1 = r0 + 8;

    for (int kt = 0; kt < NKT; kt++) {
        const int st = kt % 3;
        if (kt + 1 < NKT) cp_wait<1>(); else cp_wait<0>();
        __syncthreads();
        if (kt + 2 < NKT) {
            int nx = kt + 2;
            load_kv(nx, nx % 3);
        }

        const uint32_t sKa = sbase + st * FAH_STAGE;
        const uint32_t sVa = sKa + 64 * 136 * 2;
        const uint32_t sPa = sbase + FAH_P_OFF;
        __half* sP = (__half*)(smch + FAH_P_OFF);

        // ---- S = Q @ K^T (batched K-fragment loads per ks) -----------------
        float c[8][4];
#pragma unroll
        for (int i = 0; i < 8; i++)
#pragma unroll
            for (int r = 0; r < 4; r++) c[i][r] = 0.f;
#pragma unroll
        for (int ks = 0; ks < 8; ks++) {
            uint32_t b[4][4];
#pragma unroll
            for (int p = 0; p < 4; p++)
                ldsm4(b[p][0], b[p][1], b[p][2], b[p][3],
                      sKa + ((p * 16 + keyrow) * 136 + ks * 16 + doff) * 2);
#pragma unroll
            for (int p = 0; p < 4; p++) {
                mma_f16(c[2 * p],     qf[ks], b[p][0], b[p][1]);
                mma_f16(c[2 * p + 1], qf[ks], b[p][2], b[p][3]);
            }
        }

        // ---- mask, p = exp(s*SC)/16, sum l, store P fp16 -------------------
        const int cb = kt * 64;
        const bool diag = (kt >= 2 * by);
#pragma unroll
        for (int ni = 0; ni < 8; ni++) {
            const int col = cb + ni * 8 + ti * 2;
            float s0 = c[ni][0], s1 = c[ni][1], s2 = c[ni][2], s3 = c[ni][3];
            if (diag) {
                if (col > r0)     s0 = -1e30f;
                if (col + 1 > r0) s1 = -1e30f;
                if (col > r1)     s2 = -1e30f;
                if (col + 1 > r1) s3 = -1e30f;
            }
            const float p0 = __expf(s0 * SC) * 0.0625f;
            const float p1 = __expf(s1 * SC) * 0.0625f;
            const float p2 = __expf(s2 * SC) * 0.0625f;
            const float p3 = __expf(s3 * SC) * 0.0625f;
            ls0 += p0 + p1;
            ls1 += p2 + p3;
            *(__half2*)&sP[(wr + gi) * 72 + ni * 8 + ti * 2]     = __floats2half2_rn(p0, p1);
            *(__half2*)&sP[(wr + gi + 8) * 72 + ni * 8 + ti * 2] = __floats2half2_rn(p2, p3);
        }
        __syncwarp();   // P region is warp-private; order STS before ldmatrix

        // ---- O += P @ V (batched V-fragment loads) -------------------------
#pragma unroll
        for (int ks = 0; ks < 4; ks++) {
            uint32_t a[4];
            ldsm4(a[0], a[1], a[2], a[3],
                  sPa + ((wr + rowl) * 72 + ks * 16 + off8) * 2);
#pragma unroll
            for (int g = 0; g < 2; g++) {
                uint32_t vb[4][4];
#pragma unroll
                for (int p = 0; p < 4; p++)
                    ldsm4t(vb[p][0], vb[p][1], vb[p][2], vb[p][3],
                           sVa + ((ks * 16 + rowl) * 136 + (g * 4 + p) * 16 + off8) * 2);
#pragma unroll
                for (int p = 0; p < 4; p++) {
                    mma_f16(o[2 * (g * 4 + p)],     a, vb[p][0], vb[p][1]);
                    mma_f16(o[2 * (g * 4 + p) + 1], a, vb[p][2], vb[p][3]);
                }
            }
        }
    }

    // ---- normalize + store fp16 (1/16 scale cancels: O/ls) -----------------
    ls0 += __shfl_xor_sync(0xffffffffu, ls0, 1);
    ls0 += __shfl_xor_sync(0xffffffffu, ls0, 2);
    ls1 += __shfl_xor_sync(0xffffffffu, ls1, 1);
    ls1 += __shfl_xor_sync(0xffffffffu, ls1, 2);
    const float i0 = 1.0f / ls0, i1 = 1.0f / ls1;
#pragma unroll
    for (int ni = 0; ni < 16; ni++) {
        const int col = h * HD_DIM + ni * 8 + ti * 2;
        *(__half2*)&O[(size_t)r0 * D_DIM + col] =
            __floats2half2_rn(o[ni][0] * i0, o[ni][1] * i0);
        *(__half2*)&O[(size_t)r1 * D_DIM + col] =
            __floats2half2_rn(o[ni][2] * i1, o[ni][3] * i1);
    }
}

// ================= rmsnorm: fp32 in -> fp16 out ==============================
__global__ void __launch_bounds__(256) rmsnorm_f16(
    const float* __restrict__ X, const float* __restrict__ W,
    __half* __restrict__ Y)
{
    const int row = blockIdx.x;
    const float* x = X + (size_t)row * D_DIM;
    float ss = 0.f;
    for (int j = threadIdx.x; j < D_DIM; j += 256) { float v = x[j]; ss += v * v; }
    __shared__ float red[256];
    red[threadIdx.x] = ss;
    __syncthreads();
    for (int off = 128; off > 0; off >>= 1) {
        if (threadIdx.x < off) red[threadIdx.x] += red[threadIdx.x + off];
        __syncthreads();
    }
    const float scale = rsqrtf(red[0] * (1.0f / D_DIM) + 1e-6f);
    __half* y = Y + (size_t)row * D_DIM;
    for (int j = threadIdx.x * 2; j < D_DIM; j += 512) {
        float2 v = *(const float2*)&x[j];
        *(__half2*)&y[j] = __floats2half2_rn(v.x * scale * W[j],
                                             v.y * scale * W[j + 1]);
    }
}

// ================= launch =====================================================
extern "C" void kernel_launch(void* const* d_in, const int* in_sizes, int n_in,
                              void* d_out, int out_size)
{
    const float* x    = (const float*)d_in[0];
    const float* wq   = (const float*)d_in[1];
    const float* wk   = (const float*)d_in[2];
    const float* wv   = (const float*)d_in[3];
    const float* wo   = (const float*)d_in[4];
    const float* w1   = (const float*)d_in[5];
    const float* w2   = (const float*)d_in[6];
    const float* w3   = (const float*)d_in[7];
    const float* anw  = (const float*)d_in[8];
    const float* fnw  = (const float*)d_in[9];
    const float* cosb = (const float*)d_in[10];
    const float* sinb = (const float*)d_in[11];
    float* out = (float*)d_out;

    __half *hn, *q, *k, *v, *attn, *fn, *ff1;
    __half *wq16, *wk16, *wv16, *wo16, *w116, *w316, *w216;
    float *h;
    cudaGetSymbolAddress((void**)&hn, g_hn);
    cudaGetSymbolAddress((void**)&q, g_q);
    cudaGetSymbolAddress((void**)&k, g_k);
    cudaGetSymbolAddress((void**)&v, g_v);
    cudaGetSymbolAddress((void**)&attn, g_attn);
    cudaGetSymbolAddress((void**)&h, g_h);
    cudaGetSymbolAddress((void**)&fn, g_fn);
    cudaGetSymbolAddress((void**)&ff1, g_ff1);
    cudaGetSymbolAddress((void**)&wq16, g_wq16);
    cudaGetSymbolAddress((void**)&wk16, g_wk16);
    cudaGetSymbolAddress((void**)&wv16, g_wv16);
    cudaGetSymbolAddress((void**)&wo16, g_wo16);
    cudaGetSymbolAddress((void**)&w116, g_w116);
    cudaGetSymbolAddress((void**)&w316, g_w316);
    cudaGetSymbolAddress((void**)&w216, g_w216);

    cudaFuncSetAttribute(mma_big<0>,
                         cudaFuncAttributeMaxDynamicSharedMemorySize, BIG_SMEM_BYTES);
    cudaFuncSetAttribute(mma_big<1>,
                         cudaFuncAttributeMaxDynamicSharedMemorySize, BIG_SMEM_BYTES);
    cudaFuncSetAttribute(flash_attn,
                         cudaFuncAttributeMaxDynamicSharedMemorySize, FAH_SMEM_BYTES);

    // Side stream for weight conversion, forked/joined inside the capture.
    // Created fresh per call (host-side objects only; kernel_launch runs a
    // handful of times, replays use the captured graph).
    cudaStream_t s2;
    cudaStreamCreateWithFlags(&s2, cudaStreamNonBlocking);
    cudaEvent_t evFork, evQKVw, evRestw;
    cudaEventCreateWithFlags(&evFork,  cudaEventDisableTiming);
    cudaEventCreateWithFlags(&evQKVw,  cudaEventDisableTiming);
    cudaEventCreateWithFlags(&evRestw, cudaEventDisableTiming);

    const size_t nd4 = (size_t)D_DIM * D_DIM / 4, nf4 = (size_t)D_DIM * FF_DIM / 4;

    // fork: s2 converts weights while main stream computes
    cudaEventRecord(evFork, 0);
    cudaStreamWaitEvent(s2, evFork, 0);
    cvt_f16<<<4096, 256, 0, s2>>>((const float4*)wq, (uint2*)wq16, nd4);
    cvt_f16<<<4096, 256, 0, s2>>>((const float4*)wk, (uint2*)wk16, nd4);
    cvt_f16<<<4096, 256, 0, s2>>>((const float4*)wv, (uint2*)wv16, nd4);
    cudaEventRecord(evQKVw, s2);
    cvt_f16<<<4096, 256, 0, s2>>>((const float4*)wo, (uint2*)wo16, nd4);
    cvt_f16<<<8192, 256, 0, s2>>>((const float4*)w1, (uint2*)w116, nf4);
    cvt_f16<<<8192, 256, 0, s2>>>((const float4*)w3, (uint2*)w316, nf4);
    cvt_f16<<<8192, 256, 0, s2>>>((const float4*)w2, (uint2*)w216, nf4);
    cudaEventRecord(evRestw, s2);

    // 1) attn rmsnorm -> fp16 (overlaps qkv weight cvt)
    rmsnorm_f16<<<S_LEN, 256>>>(x, anw, hn);

    // 2) fused QKV projection (RoPE fused for q,k) — needs wq16/wk16/wv16
    cudaStreamWaitEvent(0, evQKVw, 0);
    mma_big<1><<<dim3(48, S_LEN / 128), 256, BIG_SMEM_BYTES>>>(
        hn, D_DIM, wq16, wk16, wv16, D_DIM, q, k, v, D_DIM, D_DIM,
        nullptr, 0, nullptr, 0, cosb, sinb, /*rope_mask=*/0b011);

    // 3) fused attention (heavy-first 1D grid); overlaps wo/w1/w3/w2 cvt
    flash_attn<<<512, 256, FAH_SMEM_BYTES>>>(q, k, v, attn);

    // 4) h = x + attn @ wo   (fp32 out) — needs remaining weights
    cudaStreamWaitEvent(0, evRestw, 0);
    mma_big<0><<<dim3(16, S_LEN / 128), 256, BIG_SMEM_BYTES>>>(
        attn, D_DIM, wo16, nullptr, nullptr, D_DIM, h, nullptr, nullptr, D_DIM,
        D_DIM, x, D_DIM, nullptr, 0, nullptr, nullptr, 0);

    // 5) ffn rmsnorm -> fp16
    rmsnorm_f16<<<S_LEN, 256>>>(h, fnw, fn);

    // 6) FFN up: ff1 = fn@w1 ; then ff1 = silu(ff1) * (fn@w3)
    const dim3 gff(FF_DIM / 256, S_LEN / 128);
    mma_big<1><<<gff, 256, BIG_SMEM_BYTES>>>(
        fn, D_DIM, w116, nullptr, nullptr, FF_DIM, ff1, nullptr, nullptr, FF_DIM,
        D_DIM, nullptr, 0, nullptr, 0, nullptr, nullptr, 0);
    mma_big<1><<<gff, 256, BIG_SMEM_BYTES>>>(
        fn, D_DIM, w316, nullptr, nullptr, FF_DIM, ff1, nullptr, nullptr, FF_DIM,
        D_DIM, nullptr, 0, ff1, FF_DIM, nullptr, nullptr, 0);

    // 7) out = h + gated @ w2  (fp32 out)
    mma_big<0><<<dim3(16, S_LEN / 128), 256, BIG_SMEM_BYTES>>>(
        ff1, FF_DIM, w216, nullptr, nullptr, D_DIM, out, nullptr, nullptr, D_DIM,
        FF_DIM, h, D_DIM, nullptr, 0, nullptr, nullptr, 0);
}